// round 2
// baseline (speedup 1.0000x reference)
#include <cuda_runtime.h>
#include <cuda_bf16.h>
#include <math.h>

// Problem constants
#define NN 8192
#define DD 512
#define SCALE 0.044194173824159216f  // 1/sqrt(512)

// ---------------- scratch (no allocation allowed -> device globals) ----------------
__device__ float g_lQ[NN * DD];
__device__ float g_lK[NN * DD];
__device__ float g_lV[NN * DD];
__device__ float g_gQ[NN * DD];
__device__ float g_eV[NN * DD];
__device__ float g_es[NN];
__device__ float g_gK[DD];
__device__ float g_gV[DD];
__device__ float g_xbar[DD];
__device__ float g_part[256 * DD];
__device__ int   g_adj_mode;  // 0=int32, 1=uint8, 2=float32

// ---------------- adjacency dtype detection ----------------
__global__ void detect_adj_kernel(const unsigned int* __restrict__ w) {
    __shared__ int f_float, f_other;
    if (threadIdx.x == 0) { f_float = 0; f_other = 0; }
    __syncthreads();
    for (int i = threadIdx.x; i < 4096; i += 256) {
        unsigned int v = w[i];
        if (v == 0x3F800000u) atomicOr(&f_float, 1);
        else if (v > 1u) atomicOr(&f_other, 1);
    }
    __syncthreads();
    if (threadIdx.x == 0) g_adj_mode = f_float ? 2 : (f_other ? 1 : 0);
}

__device__ __forceinline__ bool read_adj(const void* adj, size_t idx, int mode) {
    if (mode == 0) return ((const int*)adj)[idx] != 0;
    if (mode == 1) return ((const unsigned char*)adj)[idx] != 0;
    return ((const float*)adj)[idx] != 0.0f;
}

// ---------------- column mean of x ----------------
__global__ void mean_p1_kernel(const float* __restrict__ x) {
    int b = blockIdx.x;           // 256 blocks, 32 rows each
    int t = threadIdx.x;          // 256 threads
    float s0 = 0.f, s1 = 0.f;
    for (int r = 0; r < 32; r++) {
        const float* row = x + (size_t)(b * 32 + r) * DD;
        s0 += row[t];
        s1 += row[t + 256];
    }
    g_part[(size_t)b * DD + t] = s0;
    g_part[(size_t)b * DD + t + 256] = s1;
}

__global__ void mean_p2_kernel() {
    int t = threadIdx.x;  // 512 threads
    float s = 0.f;
    for (int b = 0; b < 256; b++) s += g_part[(size_t)b * DD + t];
    g_xbar[t] = s * (1.0f / NN);
}

// ---------------- gK = xbar@Wgk ; gV = xbar@Wgv + bgv ----------------
__global__ void gkv_kernel(const float* __restrict__ Wgk, const float* __restrict__ Wgv,
                           const float* __restrict__ bgv) {
    __shared__ float xb[DD];
    int t = threadIdx.x;  // 512 threads, 2 blocks
    xb[t] = g_xbar[t];
    __syncthreads();
    const float* W = blockIdx.x ? Wgv : Wgk;
    float s = blockIdx.x ? bgv[t] : 0.0f;
    for (int k = 0; k < DD; k++) s += xb[k] * W[(size_t)k * DD + t];
    if (blockIdx.x) g_gV[t] = s; else g_gK[t] = s;
}

// ---------------- es = masked_x @ Wes ----------------
__global__ void es_kernel(const float* __restrict__ mx, const float* __restrict__ Wes) {
    __shared__ float w[DD];
    for (int d = threadIdx.x; d < DD; d += 256) w[d] = Wes[d];
    __syncthreads();
    int lane = threadIdx.x & 31;
    int wid = threadIdx.x >> 5;
    int row = blockIdx.x * 8 + wid;
    const float* r = mx + (size_t)row * DD;
    float s = 0.f;
    for (int k = lane; k < DD; k += 32) s += r[k] * w[k];
    #pragma unroll
    for (int o = 16; o; o >>= 1) s += __shfl_xor_sync(0xffffffffu, s, o);
    if (lane == 0) g_es[row] = s;
}

// ---------------- fp32 SGEMM: C[M,512] = A[M,512] @ B[512,512] (+bias) ----------------
__global__ __launch_bounds__(256) void sgemm512_kernel(
    const float* __restrict__ A, const float* __restrict__ B,
    const float* __restrict__ bias, float* __restrict__ C) {
    const int K = DD;
    __shared__ float As[16][128];
    __shared__ float Bs[16][128];
    int tid = threadIdx.x;
    int brow = blockIdx.y * 128;
    int bcol = blockIdx.x * 128;
    int tx = tid & 15, ty = tid >> 4;

    int arow = tid >> 2;            // 0..63
    int acol = (tid & 3) * 4;       // 0,4,8,12
    int browl = tid >> 5;           // 0..7
    int bcoll = (tid & 31) * 4;     // 0..124

    float acc[8][8];
    #pragma unroll
    for (int i = 0; i < 8; i++)
        #pragma unroll
        for (int j = 0; j < 8; j++) acc[i][j] = 0.f;

    for (int k0 = 0; k0 < K; k0 += 16) {
        float4 a0 = *(const float4*)&A[(size_t)(brow + arow) * K + k0 + acol];
        float4 a1 = *(const float4*)&A[(size_t)(brow + arow + 64) * K + k0 + acol];
        float4 b0 = *(const float4*)&B[(size_t)(k0 + browl) * DD + bcol + bcoll];
        float4 b1 = *(const float4*)&B[(size_t)(k0 + browl + 8) * DD + bcol + bcoll];
        __syncthreads();
        As[acol + 0][arow] = a0.x; As[acol + 1][arow] = a0.y;
        As[acol + 2][arow] = a0.z; As[acol + 3][arow] = a0.w;
        As[acol + 0][arow + 64] = a1.x; As[acol + 1][arow + 64] = a1.y;
        As[acol + 2][arow + 64] = a1.z; As[acol + 3][arow + 64] = a1.w;
        *(float4*)&Bs[browl][bcoll] = b0;
        *(float4*)&Bs[browl + 8][bcoll] = b1;
        __syncthreads();
        #pragma unroll
        for (int kk = 0; kk < 16; kk++) {
            float a[8], b[8];
            #pragma unroll
            for (int i = 0; i < 8; i++) a[i] = As[kk][ty * 8 + i];
            #pragma unroll
            for (int j = 0; j < 8; j++) b[j] = Bs[kk][tx * 8 + j];
            #pragma unroll
            for (int i = 0; i < 8; i++)
                #pragma unroll
                for (int j = 0; j < 8; j++) acc[i][j] += a[i] * b[j];
        }
    }
    float b8[8];
    #pragma unroll
    for (int j = 0; j < 8; j++) b8[j] = bias ? bias[bcol + tx * 8 + j] : 0.f;
    #pragma unroll
    for (int i = 0; i < 8; i++) {
        float* cp = C + (size_t)(brow + ty * 8 + i) * DD + bcol + tx * 8;
        float4 v0, v1;
        v0.x = acc[i][0] + b8[0]; v0.y = acc[i][1] + b8[1];
        v0.z = acc[i][2] + b8[2]; v0.w = acc[i][3] + b8[3];
        v1.x = acc[i][4] + b8[4]; v1.y = acc[i][5] + b8[5];
        v1.z = acc[i][6] + b8[6]; v1.w = acc[i][7] + b8[7];
        *(float4*)cp = v0;
        *(float4*)(cp + 4) = v1;
    }
}

// ---------------- block reductions ----------------
__device__ __forceinline__ float warp_sum(float v) {
    #pragma unroll
    for (int o = 16; o; o >>= 1) v += __shfl_xor_sync(0xffffffffu, v, o);
    return v;
}

// ---------------- sparse attention + epilogue ----------------
__global__ __launch_bounds__(256) void attn_kernel(const void* __restrict__ adj,
                                                   const float* __restrict__ mx,
                                                   float* __restrict__ out) {
    const int i = blockIdx.x;
    const int tid = threadIdx.x;
    const int lane = tid & 31, wid = tid >> 5;
    const int mode = g_adj_mode;

    __shared__ float sQ[DD];
    __shared__ int   nidx[2048];
    __shared__ float sS[2048];
    __shared__ float s_red[8];
    __shared__ int   s_iw[8];
    __shared__ int   s_cnt;

    // load Q row
    sQ[tid] = g_lQ[(size_t)i * DD + tid];
    sQ[tid + 256] = g_lQ[(size_t)i * DD + tid + 256];

    // global score g = scale * dot(gQ[i], gK)
    float p = g_gQ[(size_t)i * DD + tid] * g_gK[tid] +
              g_gQ[(size_t)i * DD + tid + 256] * g_gK[tid + 256];
    __syncthreads();
    {   // block sum of p -> s_red[0]
        float v = warp_sum(p);
        if (lane == 0) s_red[wid] = v;
        __syncthreads();
        if (tid == 0) { float t = 0; for (int w = 0; w < 8; w++) t += s_red[w]; s_red[0] = t; }
        __syncthreads();
    }
    float gsc = s_red[0] * SCALE;
    __syncthreads();
    float esc = g_es[i];
    float m = fmaxf(gsc, esc);
    float pg = expf(gsc - m), pe = expf(esc - m);
    float denom = pg + pe;
    float acc0 = pg * g_gV[tid] + pe * g_eV[(size_t)i * DD + tid];
    float acc1 = pg * g_gV[tid + 256] + pe * g_eV[(size_t)i * DD + tid + 256];

    for (int c0 = 0; c0 < NN; c0 += 2048) {
        // deterministic compaction: thread t scans 8 consecutive columns
        int myj[8]; int mc = 0;
        int base = c0 + tid * 8;
        #pragma unroll
        for (int u = 0; u < 8; u++) {
            if (read_adj(adj, (size_t)i * NN + base + u, mode)) myj[mc++] = base + u;
        }
        int v = mc;
        #pragma unroll
        for (int o = 1; o < 32; o <<= 1) {
            int n = __shfl_up_sync(0xffffffffu, v, o);
            if (lane >= o) v += n;
        }
        if (lane == 31) s_iw[wid] = v;
        __syncthreads();
        if (tid == 0) {
            int t = 0;
            for (int w = 0; w < 8; w++) { int x = s_iw[w]; s_iw[w] = t; t += x; }
            s_cnt = t;
        }
        __syncthreads();
        int off = s_iw[wid] + v - mc;
        for (int u = 0; u < mc; u++) nidx[off + u] = myj[u];
        __syncthreads();
        int cnt = s_cnt;
        if (cnt == 0) { __syncthreads(); continue; }

        // scores: one warp per neighbor
        for (int t = wid; t < cnt; t += 8) {
            const float* kr = g_lK + (size_t)nidx[t] * DD;
            float s = 0.f;
            #pragma unroll
            for (int kk = 0; kk < 16; kk++) s += sQ[lane + kk * 32] * kr[lane + kk * 32];
            s = warp_sum(s);
            if (lane == 0) sS[t] = s * SCALE;
        }
        __syncthreads();

        // chunk max
        float cm = -3.0e38f;
        for (int t = tid; t < cnt; t += 256) cm = fmaxf(cm, sS[t]);
        {
            #pragma unroll
            for (int o = 16; o; o >>= 1) cm = fmaxf(cm, __shfl_xor_sync(0xffffffffu, cm, o));
            if (lane == 0) s_red[wid] = cm;
            __syncthreads();
            if (tid == 0) { float t = -3.0e38f; for (int w = 0; w < 8; w++) t = fmaxf(t, s_red[w]); s_red[0] = t; }
            __syncthreads();
            cm = s_red[0];
            __syncthreads();
        }
        float mn = fmaxf(m, cm);
        float rs = expf(m - mn);
        acc0 *= rs; acc1 *= rs; denom *= rs;
        m = mn;

        // exponentiate + partial denom
        float dl = 0.f;
        for (int t = tid; t < cnt; t += 256) { float pv = expf(sS[t] - m); sS[t] = pv; dl += pv; }
        {
            float vsum = warp_sum(dl);
            if (lane == 0) s_red[wid] = vsum;
            __syncthreads();
            if (tid == 0) { float t = 0; for (int w = 0; w < 8; w++) t += s_red[w]; s_red[0] = t; }
            __syncthreads();
            denom += s_red[0];
            __syncthreads();
        }

        // accumulate V
        #pragma unroll 2
        for (int t = 0; t < cnt; t++) {
            float pv = sS[t];
            const float* vr = g_lV + (size_t)nidx[t] * DD;
            acc0 += pv * vr[tid];
            acc1 += pv * vr[tid + 256];
        }
        __syncthreads();
    }

    float inv = 1.0f / denom;
    size_t o = (size_t)i * DD;
    out[o + tid]       = fmaxf(acc0 * inv, mx[o + tid]);
    out[o + tid + 256] = fmaxf(acc1 * inv, mx[o + tid + 256]);
}

// ---------------- launch ----------------
extern "C" void kernel_launch(void* const* d_in, const int* in_sizes, int n_in,
                              void* d_out, int out_size) {
    const void*  adj = d_in[0];
    const float* x   = (const float*)d_in[1];
    const float* mx  = (const float*)d_in[2];
    const float* Wlq = (const float*)d_in[3];
    const float* Wlk = (const float*)d_in[4];
    const float* Wlv = (const float*)d_in[5];
    const float* blv = (const float*)d_in[6];
    const float* Wgq = (const float*)d_in[7];
    const float* Wgk = (const float*)d_in[8];
    const float* Wgv = (const float*)d_in[9];
    const float* bgv = (const float*)d_in[10];
    const float* Wes = (const float*)d_in[11];
    const float* Wev = (const float*)d_in[12];
    const float* bev = (const float*)d_in[13];
    float* out = (float*)d_out;

    float *pLQ, *pLK, *pLV, *pGQ, *pEV;
    cudaGetSymbolAddress((void**)&pLQ, g_lQ);
    cudaGetSymbolAddress((void**)&pLK, g_lK);
    cudaGetSymbolAddress((void**)&pLV, g_lV);
    cudaGetSymbolAddress((void**)&pGQ, g_gQ);
    cudaGetSymbolAddress((void**)&pEV, g_eV);

    detect_adj_kernel<<<1, 256>>>((const unsigned int*)adj);
    mean_p1_kernel<<<256, 256>>>(x);
    mean_p2_kernel<<<1, 512>>>();
    gkv_kernel<<<2, 512>>>(Wgk, Wgv, bgv);

    dim3 ggrid(4, 64);
    sgemm512_kernel<<<ggrid, 256>>>(mx, Wlq, nullptr, pLQ);
    sgemm512_kernel<<<ggrid, 256>>>(x,  Wlk, nullptr, pLK);
    sgemm512_kernel<<<ggrid, 256>>>(x,  Wlv, blv,     pLV);
    sgemm512_kernel<<<ggrid, 256>>>(mx, Wgq, nullptr, pGQ);
    sgemm512_kernel<<<ggrid, 256>>>(mx, Wev, bev,     pEV);

    es_kernel<<<1024, 256>>>(mx, Wes);
    attn_kernel<<<NN, 256>>>(adj, mx, out);
}

// round 8
// speedup vs baseline: 1.0580x; 1.0580x over previous
#include <cuda_runtime.h>
#include <cuda_bf16.h>
#include <math.h>
#include <stdint.h>

// Problem constants
#define NN 8192
#define DD 512
#define SCALE 0.044194173824159216f  // 1/sqrt(512)

// ---------------- scratch (no allocation allowed -> device globals) ----------------
__device__ float g_lQ[NN * DD];
__device__ float g_lK[NN * DD];
__device__ float g_lV[NN * DD];
__device__ float g_gQ[NN * DD];
__device__ float g_eV[NN * DD];
__device__ float g_WT[5 * DD * DD];   // transposed weights [N][K]
__device__ float g_es[NN];
__device__ float g_gK[DD];
__device__ float g_gV[DD];
__device__ float g_xbar[DD];
__device__ float g_part[256 * DD];
__device__ int   g_adj_mode;  // 0=int32, 1=uint8, 2=float32
__device__ int   g_fb;        // 1 => tensor-core GEMM failed spot-check, FFMA fallback runs

// ---------------- tf32 helpers (family-portable PTX, sm_80+) ----------------
__device__ __forceinline__ void split_tf32(float v, uint32_t& h, uint32_t& l) {
    uint32_t hb;
    asm("cvt.rna.tf32.f32 %0, %1;" : "=r"(hb) : "f"(v));
    float lf = v - __uint_as_float(hb);
    uint32_t lb;
    asm("cvt.rna.tf32.f32 %0, %1;" : "=r"(lb) : "f"(lf));
    h = hb; l = lb;
}

__device__ __forceinline__ void mma8(float d[4], const uint32_t a[4], const uint32_t b[2]) {
    asm volatile(
        "mma.sync.aligned.m16n8k8.row.col.f32.tf32.tf32.f32 "
        "{%0,%1,%2,%3}, {%4,%5,%6,%7}, {%8,%9}, {%0,%1,%2,%3};"
        : "+f"(d[0]), "+f"(d[1]), "+f"(d[2]), "+f"(d[3])
        : "r"(a[0]), "r"(a[1]), "r"(a[2]), "r"(a[3]), "r"(b[0]), "r"(b[1]));
}

// ---------------- adjacency dtype detection (+ flag reset) ----------------
__global__ void detect_adj_kernel(const unsigned int* __restrict__ w) {
    __shared__ int f_float, f_other;
    if (threadIdx.x == 0) { f_float = 0; f_other = 0; g_fb = 0; }
    __syncthreads();
    for (int i = threadIdx.x; i < 4096; i += 256) {
        unsigned int v = w[i];
        if (v == 0x3F800000u) atomicOr(&f_float, 1);
        else if (v > 1u) atomicOr(&f_other, 1);
    }
    __syncthreads();
    if (threadIdx.x == 0) g_adj_mode = f_float ? 2 : (f_other ? 1 : 0);
}

__device__ __forceinline__ bool read_adj(const void* adj, size_t idx, int mode) {
    if (mode == 0) return ((const int*)adj)[idx] != 0;
    if (mode == 1) return ((const unsigned char*)adj)[idx] != 0;
    return ((const float*)adj)[idx] != 0.0f;
}

// ---------------- column mean of x ----------------
__global__ void mean_p1_kernel(const float* __restrict__ x) {
    int b = blockIdx.x;
    int t = threadIdx.x;
    float s0 = 0.f, s1 = 0.f;
    for (int r = 0; r < 32; r++) {
        const float* row = x + (size_t)(b * 32 + r) * DD;
        s0 += row[t];
        s1 += row[t + 256];
    }
    g_part[(size_t)b * DD + t] = s0;
    g_part[(size_t)b * DD + t + 256] = s1;
}

__global__ void mean_p2_kernel() {
    int t = threadIdx.x;
    float s = 0.f;
    for (int b = 0; b < 256; b++) s += g_part[(size_t)b * DD + t];
    g_xbar[t] = s * (1.0f / NN);
}

// ---------------- gK = xbar@Wgk ; gV = xbar@Wgv + bgv ----------------
__global__ void gkv_kernel(const float* __restrict__ Wgk, const float* __restrict__ Wgv,
                           const float* __restrict__ bgv) {
    __shared__ float xb[DD];
    int tid = threadIdx.x;
    for (int d = tid; d < DD; d += 128) xb[d] = g_xbar[d];
    __syncthreads();
    int mat = blockIdx.x >> 2;
    int col = (blockIdx.x & 3) * 128 + tid;
    const float* W = mat ? Wgv : Wgk;
    float s = mat ? bgv[col] : 0.0f;
    for (int k = 0; k < DD; k++) s += xb[k] * W[(size_t)k * DD + col];
    if (mat) g_gV[col] = s; else g_gK[col] = s;
}

// ---------------- es = masked_x @ Wes ----------------
__global__ void es_kernel(const float* __restrict__ mx, const float* __restrict__ Wes) {
    __shared__ float w[DD];
    for (int d = threadIdx.x; d < DD; d += 256) w[d] = Wes[d];
    __syncthreads();
    int lane = threadIdx.x & 31;
    int wid = threadIdx.x >> 5;
    int row = blockIdx.x * 8 + wid;
    const float* r = mx + (size_t)row * DD;
    float s = 0.f;
    for (int k = lane; k < DD; k += 32) s += r[k] * w[k];
    #pragma unroll
    for (int o = 16; o; o >>= 1) s += __shfl_xor_sync(0xffffffffu, s, o);
    if (lane == 0) g_es[row] = s;
}

// ---------------- weight transpose: g_WT[z][n][k] = W_z[k][n] ----------------
__global__ void transpose_w_kernel(const float* __restrict__ w0, const float* __restrict__ w1,
                                   const float* __restrict__ w2, const float* __restrict__ w3,
                                   const float* __restrict__ w4) {
    __shared__ float t[32][33];
    const float* src;
    switch (blockIdx.z) {
        case 0: src = w0; break;
        case 1: src = w1; break;
        case 2: src = w2; break;
        case 3: src = w3; break;
        default: src = w4; break;
    }
    float* dst = g_WT + (size_t)blockIdx.z * DD * DD;
    int x = blockIdx.x * 32 + threadIdx.x;  // n
    int y = blockIdx.y * 32 + threadIdx.y;  // k
    #pragma unroll
    for (int j = 0; j < 4; j++)
        t[threadIdx.y + j * 8][threadIdx.x] = src[(size_t)(y + j * 8) * DD + x];
    __syncthreads();
    int x2 = blockIdx.y * 32 + threadIdx.x;  // k
    int y2 = blockIdx.x * 32 + threadIdx.y;  // n
    #pragma unroll
    for (int j = 0; j < 4; j++)
        dst[(size_t)(y2 + j * 8) * DD + x2] = t[threadIdx.x][threadIdx.y + j * 8];
}

// ---------------- 3xTF32 mma.sync GEMM: C[M,512] = A[M,512] @ B ; BT = B^T [N][K] ----------------
// CTA 128x128, 8 warps x (64x32), k-chunk 32. Smem: A/B tiles n-major [128][36] hi+lo.
#define TSTRIDE 36
#define TBUF    (128 * TSTRIDE)           // 4608 words
#define SM_TOTAL (4 * TBUF * 4)           // 73728 bytes

__global__ __launch_bounds__(256) void tc_gemm_kernel(
    const float* __restrict__ A, const float* __restrict__ BT,
    const float* __restrict__ bias, float* __restrict__ C) {
    extern __shared__ uint32_t sm[];
    uint32_t* Ah = sm;
    uint32_t* Al = sm + TBUF;
    uint32_t* Bh = sm + 2 * TBUF;
    uint32_t* Bl = sm + 3 * TBUF;

    const int tid = threadIdx.x;
    const int wid = tid >> 5, lane = tid & 31;
    const int gid = lane >> 2, tig = lane & 3;
    const int warp_m = wid & 1;            // 2 x 64 rows
    const int warp_n = wid >> 1;           // 4 x 32 cols
    const int brow = blockIdx.y * 128;
    const int bcol = blockIdx.x * 128;

    float d[4][4][4];
    #pragma unroll
    for (int mi = 0; mi < 4; mi++)
        #pragma unroll
        for (int nj = 0; nj < 4; nj++)
            #pragma unroll
            for (int r = 0; r < 4; r++) d[mi][nj][r] = 0.f;

    for (int kt = 0; kt < 16; kt++) {
        const int k0 = kt * 32;
        // load + split: 128 rows x 8 float4 per tensor
        #pragma unroll
        for (int g = tid; g < 1024; g += 256) {
            const int row = g >> 3, c4 = (g & 7) * 4;
            float4 va = *(const float4*)&A[(size_t)(brow + row) * DD + k0 + c4];
            float4 vb = *(const float4*)&BT[(size_t)(bcol + row) * DD + k0 + c4];
            uint4 ah, al, bh, bl;
            split_tf32(va.x, ah.x, al.x); split_tf32(va.y, ah.y, al.y);
            split_tf32(va.z, ah.z, al.z); split_tf32(va.w, ah.w, al.w);
            split_tf32(vb.x, bh.x, bl.x); split_tf32(vb.y, bh.y, bl.y);
            split_tf32(vb.z, bh.z, bl.z); split_tf32(vb.w, bh.w, bl.w);
            const int o = row * TSTRIDE + c4;
            *(uint4*)&Ah[o] = ah; *(uint4*)&Al[o] = al;
            *(uint4*)&Bh[o] = bh; *(uint4*)&Bl[o] = bl;
        }
        __syncthreads();
        #pragma unroll
        for (int ks = 0; ks < 4; ks++) {
            const int kk = ks * 8;
            // B fragments for 4 n-atoms (hi+lo)
            uint32_t bhf[4][2], blf[4][2];
            #pragma unroll
            for (int nj = 0; nj < 4; nj++) {
                const int nbase = (warp_n * 32 + nj * 8 + gid) * TSTRIDE + kk;
                bhf[nj][0] = Bh[nbase + tig];     bhf[nj][1] = Bh[nbase + tig + 4];
                blf[nj][0] = Bl[nbase + tig];     blf[nj][1] = Bl[nbase + tig + 4];
            }
            #pragma unroll
            for (int mi = 0; mi < 4; mi++) {
                const int r0 = (warp_m * 64 + mi * 16 + gid) * TSTRIDE + kk;
                uint32_t ahf[4], alf[4];
                ahf[0] = Ah[r0 + tig];                 ahf[1] = Ah[r0 + 8 * TSTRIDE + tig];
                ahf[2] = Ah[r0 + tig + 4];             ahf[3] = Ah[r0 + 8 * TSTRIDE + tig + 4];
                alf[0] = Al[r0 + tig];                 alf[1] = Al[r0 + 8 * TSTRIDE + tig];
                alf[2] = Al[r0 + tig + 4];             alf[3] = Al[r0 + 8 * TSTRIDE + tig + 4];
                #pragma unroll
                for (int nj = 0; nj < 4; nj++) {
                    mma8(d[mi][nj], ahf, bhf[nj]);
                    mma8(d[mi][nj], ahf, blf[nj]);
                    mma8(d[mi][nj], alf, bhf[nj]);
                }
            }
        }
        __syncthreads();
    }

    // epilogue
    #pragma unroll
    for (int mi = 0; mi < 4; mi++) {
        const int row0 = brow + warp_m * 64 + mi * 16 + gid;
        #pragma unroll
        for (int nj = 0; nj < 4; nj++) {
            const int col0 = bcol + warp_n * 32 + nj * 8 + tig * 2;
            float b0 = bias ? bias[col0] : 0.f;
            float b1 = bias ? bias[col0 + 1] : 0.f;
            float2 v0 = make_float2(d[mi][nj][0] + b0, d[mi][nj][1] + b1);
            float2 v1 = make_float2(d[mi][nj][2] + b0, d[mi][nj][3] + b1);
            *(float2*)&C[(size_t)row0 * DD + col0] = v0;
            *(float2*)&C[(size_t)(row0 + 8) * DD + col0] = v1;
        }
    }
}

// ---------------- block reductions ----------------
__device__ __forceinline__ float warp_sum(float v) {
    #pragma unroll
    for (int o = 16; o; o >>= 1) v += __shfl_xor_sync(0xffffffffu, v, o);
    return v;
}

// ---------------- GEMM spot-checker: sampled FFMA recompute vs tensor-core output ----------------
__global__ void check_gemm_kernel(const float* __restrict__ A, const float* __restrict__ W,
                                  const float* __restrict__ bias, const float* __restrict__ C) {
    int gw = blockIdx.x * 8 + (threadIdx.x >> 5);   // 64 warps over 8 blocks
    int lane = threadIdx.x & 31;
    int row = (gw * 1317 + 7) & (NN - 1);
    int col = (gw * 371 + 11) & (DD - 1);
    float s = 0.f;
    const float* ar = A + (size_t)row * DD;
    for (int k = lane; k < DD; k += 32) s += ar[k] * W[(size_t)k * DD + col];
    s = warp_sum(s);
    if (lane == 0) {
        if (bias) s += bias[col];
        float c = C[(size_t)row * DD + col];
        if (fabsf(c - s) > 5e-3f * (fabsf(s) + 1.0f)) g_fb = 1;
    }
}

// ---------------- FFMA fallback SGEMM (early-exits when tensor output verified) ----------------
__global__ __launch_bounds__(256) void sgemm512_fb_kernel(
    const float* __restrict__ A, const float* __restrict__ B,
    const float* __restrict__ bias, float* __restrict__ C) {
    if (g_fb == 0) return;
    const int K = DD;
    __shared__ float As[16][128];
    __shared__ float Bs[16][128];
    int tid = threadIdx.x;
    int brow = blockIdx.y * 128;
    int bcol = blockIdx.x * 128;
    int tx = tid & 15, ty = tid >> 4;

    int arow = tid >> 2;
    int acol = (tid & 3) * 4;
    int browl = tid >> 5;
    int bcoll = (tid & 31) * 4;

    float acc[8][8];
    #pragma unroll
    for (int i = 0; i < 8; i++)
        #pragma unroll
        for (int j = 0; j < 8; j++) acc[i][j] = 0.f;

    for (int k0 = 0; k0 < K; k0 += 16) {
        float4 a0 = *(const float4*)&A[(size_t)(brow + arow) * K + k0 + acol];
        float4 a1 = *(const float4*)&A[(size_t)(brow + arow + 64) * K + k0 + acol];
        float4 b0 = *(const float4*)&B[(size_t)(k0 + browl) * DD + bcol + bcoll];
        float4 b1 = *(const float4*)&B[(size_t)(k0 + browl + 8) * DD + bcol + bcoll];
        __syncthreads();
        As[acol + 0][arow] = a0.x; As[acol + 1][arow] = a0.y;
        As[acol + 2][arow] = a0.z; As[acol + 3][arow] = a0.w;
        As[acol + 0][arow + 64] = a1.x; As[acol + 1][arow + 64] = a1.y;
        As[acol + 2][arow + 64] = a1.z; As[acol + 3][arow + 64] = a1.w;
        *(float4*)&Bs[browl][bcoll] = b0;
        *(float4*)&Bs[browl + 8][bcoll] = b1;
        __syncthreads();
        #pragma unroll
        for (int kk = 0; kk < 16; kk++) {
            float a[8], b[8];
            #pragma unroll
            for (int i = 0; i < 8; i++) a[i] = As[kk][ty * 8 + i];
            #pragma unroll
            for (int j = 0; j < 8; j++) b[j] = Bs[kk][tx * 8 + j];
            #pragma unroll
            for (int i = 0; i < 8; i++)
                #pragma unroll
                for (int j = 0; j < 8; j++) acc[i][j] += a[i] * b[j];
        }
    }
    float b8[8];
    #pragma unroll
    for (int j = 0; j < 8; j++) b8[j] = bias ? bias[bcol + tx * 8 + j] : 0.f;
    #pragma unroll
    for (int i = 0; i < 8; i++) {
        float* cp = C + (size_t)(brow + ty * 8 + i) * DD + bcol + tx * 8;
        float4 v0, v1;
        v0.x = acc[i][0] + b8[0]; v0.y = acc[i][1] + b8[1];
        v0.z = acc[i][2] + b8[2]; v0.w = acc[i][3] + b8[3];
        v1.x = acc[i][4] + b8[4]; v1.y = acc[i][5] + b8[5];
        v1.z = acc[i][6] + b8[6]; v1.w = acc[i][7] + b8[7];
        *(float4*)cp = v0;
        *(float4*)(cp + 4) = v1;
    }
}

// ---------------- sparse attention + epilogue ----------------
__global__ __launch_bounds__(256) void attn_kernel(const void* __restrict__ adj,
                                                   const float* __restrict__ mx,
                                                   float* __restrict__ out) {
    const int i = blockIdx.x;
    const int tid = threadIdx.x;
    const int lane = tid & 31, wid = tid >> 5;
    const int mode = g_adj_mode;

    __shared__ float sQ[DD];
    __shared__ int   nidx[2048];
    __shared__ float sS[2048];
    __shared__ float s_red[8];
    __shared__ int   s_iw[8];
    __shared__ int   s_cnt;

    sQ[tid] = g_lQ[(size_t)i * DD + tid];
    sQ[tid + 256] = g_lQ[(size_t)i * DD + tid + 256];

    float p = g_gQ[(size_t)i * DD + tid] * g_gK[tid] +
              g_gQ[(size_t)i * DD + tid + 256] * g_gK[tid + 256];
    __syncthreads();
    {
        float v = warp_sum(p);
        if (lane == 0) s_red[wid] = v;
        __syncthreads();
        if (tid == 0) { float t = 0; for (int w = 0; w < 8; w++) t += s_red[w]; s_red[0] = t; }
        __syncthreads();
    }
    float gsc = s_red[0] * SCALE;
    __syncthreads();
    float esc = g_es[i];
    float m = fmaxf(gsc, esc);
    float pg = expf(gsc - m), pe = expf(esc - m);
    float denom = pg + pe;
    float acc0 = pg * g_gV[tid] + pe * g_eV[(size_t)i * DD + tid];
    float acc1 = pg * g_gV[tid + 256] + pe * g_eV[(size_t)i * DD + tid + 256];

    for (int c0 = 0; c0 < NN; c0 += 2048) {
        int myj[8]; int mc = 0;
        int base = c0 + tid * 8;
        #pragma unroll
        for (int u = 0; u < 8; u++) {
            if (read_adj(adj, (size_t)i * NN + base + u, mode)) myj[mc++] = base + u;
        }
        int v = mc;
        #pragma unroll
        for (int o = 1; o < 32; o <<= 1) {
            int n = __shfl_up_sync(0xffffffffu, v, o);
            if (lane >= o) v += n;
        }
        if (lane == 31) s_iw[wid] = v;
        __syncthreads();
        if (tid == 0) {
            int t = 0;
            for (int w = 0; w < 8; w++) { int x = s_iw[w]; s_iw[w] = t; t += x; }
            s_cnt = t;
        }
        __syncthreads();
        int off = s_iw[wid] + v - mc;
        for (int u = 0; u < mc; u++) nidx[off + u] = myj[u];
        __syncthreads();
        int cnt = s_cnt;
        if (cnt == 0) { __syncthreads(); continue; }

        for (int t = wid; t < cnt; t += 8) {
            const float* kr = g_lK + (size_t)nidx[t] * DD;
            float s = 0.f;
            #pragma unroll
            for (int kk = 0; kk < 16; kk++) s += sQ[lane + kk * 32] * kr[lane + kk * 32];
            s = warp_sum(s);
            if (lane == 0) sS[t] = s * SCALE;
        }
        __syncthreads();

        float cm = -3.0e38f;
        for (int t = tid; t < cnt; t += 256) cm = fmaxf(cm, sS[t]);
        {
            #pragma unroll
            for (int o = 16; o; o >>= 1) cm = fmaxf(cm, __shfl_xor_sync(0xffffffffu, cm, o));
            if (lane == 0) s_red[wid] = cm;
            __syncthreads();
            if (tid == 0) { float t = -3.0e38f; for (int w = 0; w < 8; w++) t = fmaxf(t, s_red[w]); s_red[0] = t; }
            __syncthreads();
            cm = s_red[0];
            __syncthreads();
        }
        float mn = fmaxf(m, cm);
        float rs = expf(m - mn);
        acc0 *= rs; acc1 *= rs; denom *= rs;
        m = mn;

        float dl = 0.f;
        for (int t = tid; t < cnt; t += 256) { float pv = expf(sS[t] - m); sS[t] = pv; dl += pv; }
        {
            float vsum = warp_sum(dl);
            if (lane == 0) s_red[wid] = vsum;
            __syncthreads();
            if (tid == 0) { float t = 0; for (int w = 0; w < 8; w++) t += s_red[w]; s_red[0] = t; }
            __syncthreads();
            denom += s_red[0];
            __syncthreads();
        }

        #pragma unroll 2
        for (int t = 0; t < cnt; t++) {
            float pv = sS[t];
            const float* vr = g_lV + (size_t)nidx[t] * DD;
            acc0 += pv * vr[tid];
            acc1 += pv * vr[tid + 256];
        }
        __syncthreads();
    }

    float inv = 1.0f / denom;
    size_t o = (size_t)i * DD;
    out[o + tid]       = fmaxf(acc0 * inv, mx[o + tid]);
    out[o + tid + 256] = fmaxf(acc1 * inv, mx[o + tid + 256]);
}

// ---------------- launch ----------------
extern "C" void kernel_launch(void* const* d_in, const int* in_sizes, int n_in,
                              void* d_out, int out_size) {
    const void*  adj = d_in[0];
    const float* x   = (const float*)d_in[1];
    const float* mx  = (const float*)d_in[2];
    const float* Wlq = (const float*)d_in[3];
    const float* Wlk = (const float*)d_in[4];
    const float* Wlv = (const float*)d_in[5];
    const float* blv = (const float*)d_in[6];
    const float* Wgq = (const float*)d_in[7];
    const float* Wgk = (const float*)d_in[8];
    const float* Wgv = (const float*)d_in[9];
    const float* bgv = (const float*)d_in[10];
    const float* Wes = (const float*)d_in[11];
    const float* Wev = (const float*)d_in[12];
    const float* bev = (const float*)d_in[13];
    float* out = (float*)d_out;

    float *pLQ, *pLK, *pLV, *pGQ, *pEV, *pWT;
    cudaGetSymbolAddress((void**)&pLQ, g_lQ);
    cudaGetSymbolAddress((void**)&pLK, g_lK);
    cudaGetSymbolAddress((void**)&pLV, g_lV);
    cudaGetSymbolAddress((void**)&pGQ, g_gQ);
    cudaGetSymbolAddress((void**)&pEV, g_eV);
    cudaGetSymbolAddress((void**)&pWT, g_WT);

    cudaFuncSetAttribute(tc_gemm_kernel, cudaFuncAttributeMaxDynamicSharedMemorySize, SM_TOTAL);

    detect_adj_kernel<<<1, 256>>>((const unsigned int*)adj);
    mean_p1_kernel<<<256, 256>>>(x);
    mean_p2_kernel<<<1, 512>>>();
    gkv_kernel<<<8, 128>>>(Wgk, Wgv, bgv);

    // weight transposes: order Wlq, Wlk, Wlv, Wgq, Wev
    transpose_w_kernel<<<dim3(16, 16, 5), dim3(32, 8)>>>(Wlq, Wlk, Wlv, Wgq, Wev);

    dim3 ggrid(4, 64);
    tc_gemm_kernel<<<ggrid, 256, SM_TOTAL>>>(mx, pWT + 0 * DD * DD, nullptr, pLQ);
    tc_gemm_kernel<<<ggrid, 256, SM_TOTAL>>>(x,  pWT + 1 * DD * DD, nullptr, pLK);
    tc_gemm_kernel<<<ggrid, 256, SM_TOTAL>>>(x,  pWT + 2 * DD * DD, blv,     pLV);
    tc_gemm_kernel<<<ggrid, 256, SM_TOTAL>>>(mx, pWT + 3 * DD * DD, nullptr, pGQ);
    tc_gemm_kernel<<<ggrid, 256, SM_TOTAL>>>(mx, pWT + 4 * DD * DD, bev,     pEV);

    // spot-check tensor outputs against FFMA samples (sets g_fb on mismatch)
    check_gemm_kernel<<<8, 256>>>(mx, Wlq, nullptr, pLQ);
    check_gemm_kernel<<<8, 256>>>(x,  Wlk, nullptr, pLK);
    check_gemm_kernel<<<8, 256>>>(x,  Wlv, blv,     pLV);
    check_gemm_kernel<<<8, 256>>>(mx, Wgq, nullptr, pGQ);
    check_gemm_kernel<<<8, 256>>>(mx, Wev, bev,     pEV);

    // deterministic FFMA fallback; early-exits when g_fb == 0
    sgemm512_fb_kernel<<<ggrid, 256>>>(mx, Wlq, nullptr, pLQ);
    sgemm512_fb_kernel<<<ggrid, 256>>>(x,  Wlk, nullptr, pLK);
    sgemm512_fb_kernel<<<ggrid, 256>>>(x,  Wlv, blv,     pLV);
    sgemm512_fb_kernel<<<ggrid, 256>>>(mx, Wgq, nullptr, pGQ);
    sgemm512_fb_kernel<<<ggrid, 256>>>(mx, Wev, bev,     pEV);

    es_kernel<<<1024, 256>>>(mx, Wes);
    attn_kernel<<<NN, 256>>>(adj, mx, out);
}